// round 1
// baseline (speedup 1.0000x reference)
#include <cuda_runtime.h>

#define HH 4096
#define WW 4096
#define W4 (WW / 4)   // 1024 quads per row

__global__ __launch_bounds__(256) void nms_kernel(
    const float* __restrict__ img,
    const float* __restrict__ theta,
    float* __restrict__ out)
{
    int idx = blockIdx.x * blockDim.x + threadIdx.x;   // quad index, 0 .. H*W4-1
    int h  = idx >> 10;            // / 1024
    int w0 = (idx & 1023) << 2;    // quad start column
    long base = (long)h * WW + w0;

    if (h == 0 || h == HH - 1) {
        *reinterpret_cast<float4*>(out + base) = make_float4(0.f, 0.f, 0.f, 0.f);
        return;
    }

    const float4 t4 = __ldg(reinterpret_cast<const float4*>(theta + base));
    const float4 c4 = __ldg(reinterpret_cast<const float4*>(img + base));
    const float4 u4 = __ldg(reinterpret_cast<const float4*>(img + base - WW));
    const float4 d4 = __ldg(reinterpret_cast<const float4*>(img + base + WW));

    // Halo scalars (clamped so the two corner cases stay in-bounds; values
    // at clamped addresses are never used because those pixels are border-zeroed).
    long uli = base - WW - 1; if (uli < 0) uli = 0;
    long dri = base + WW + 4; if (dri >= (long)HH * WW) dri = (long)HH * WW - 1;

    float lft = __ldg(img + base - 1);
    float rgt = __ldg(img + base + 4);
    float ul  = __ldg(img + uli);
    float ur  = __ldg(img + base - WW + 4);
    float dl  = __ldg(img + base + WW - 1);
    float dr  = __ldg(img + dri);

    // row[j] / u[j] / dn[j] hold the value at column (w0 - 1 + j)
    float row[6] = { lft, c4.x, c4.y, c4.z, c4.w, rgt };
    float u [6]  = { ul,  u4.x, u4.y, u4.z, u4.w, ur  };
    float dn[6]  = { dl,  d4.x, d4.y, d4.z, d4.w, dr  };
    float th[4]  = { t4.x, t4.y, t4.z, t4.w };
    float o[4];

    #pragma unroll
    for (int i = 0; i < 4; i++) {
        // --- angle quantization, bit-exact vs reference ---
        float deg = __fmul_rn(th[i], 57.29577951308232f);   // theta * f32(180/pi)
        if (deg < 0.f) deg = __fadd_rn(deg, 180.f);         // single conditional add
        float q = __fmul_rn(rintf(__fdiv_rn(deg, 45.f)), 45.f);  // rintf == jnp.round (half-even)
        if (q == 180.f) q = 0.f;

        float cc = row[i + 1];
        float a, b;
        if (q == 0.f)        { a = row[i + 2]; b = row[i];     }  // (h, w±1)
        else if (q == 45.f)  { a = dn [i + 2]; b = u  [i];     }  // (h+1,w+1),(h-1,w-1)
        else if (q == 90.f)  { a = dn [i + 1]; b = u  [i + 1]; }  // (h±1, w)
        else                 { a = dn [i];     b = u  [i + 2]; }  // (h+1,w-1),(h-1,w+1)

        o[i] = (cc >= a && cc >= b) ? cc : 0.f;
    }

    // left / right image borders
    if (w0 == 0)       o[0] = 0.f;
    if (w0 == WW - 4)  o[3] = 0.f;

    *reinterpret_cast<float4*>(out + base) = make_float4(o[0], o[1], o[2], o[3]);
}

extern "C" void kernel_launch(void* const* d_in, const int* in_sizes, int n_in,
                              void* d_out, int out_size)
{
    const float* img   = (const float*)d_in[0];
    const float* theta = (const float*)d_in[1];
    float*       out   = (float*)d_out;

    const int n_quads = HH * W4;           // 4,194,304 threads
    const int block   = 256;
    const int grid    = n_quads / block;   // 16384
    nms_kernel<<<grid, block>>>(img, theta, out);
}